// round 17
// baseline (speedup 1.0000x reference)
#include <cuda_runtime.h>
#include <cuda_fp16.h>
#include <math.h>
#include <stdint.h>

// Problem constants
#define Bb 4
#define Tt 2048
#define Cc 1024
#define Hh 8
#define HKV 4
#define Dd 128
#define Gg 512
#define HIi 8
#define DIi 64
#define NEGv (-1e30f)

#define NTOK (Bb*Tt)   // 8192
#define NCOL 4096      // fused projection width: q|ck|cv|cg | ig|iq|ik
#define OFF_Q  0
#define OFF_CK 1024
#define OFF_CV 1536
#define OFF_CG 2048
#define OFF_IG 2560
#define OFF_IQ 3072
#define OFF_IK 3584
#define SPLIT_COL 2560   // [0,2560) 2-term ; [2560,4096) 3-term (selection chain)

// plane strides (elements)
#define PL_X   ((long)NTOK*1024)
#define PL_WT  ((long)NCOL*1024)
#define PL_IQ  ((long)NTOK*512)
#define PL_IK  ((long)Bb*512*512)
#define PL_AT  ((long)NTOK*1024)
#define PL_WA  ((long)512*1024)
#define PL_RN  ((long)NTOK*512)
#define PL_WB  ((long)1024*512)

// ---------------- scratch (static device allocations) ----------------
__device__ alignas(256) __half g_xs [2*PL_X];
__device__ alignas(256) __half g_WTs[2*PL_WT];
__device__ alignas(256) float g_Pall[(size_t)NTOK*NCOL];
__device__ alignas(256) float g_ck [Bb*Gg*HKV*Dd];
__device__ alignas(256) float g_cv [Bb*Gg*HKV*Dd];
__device__ alignas(256) __half g_iks[2*PL_IK];
__device__ alignas(256) __half g_iqs[2*PL_IQ];
__device__ alignas(256) float g_isc[NTOK*Gg];
__device__ alignas(256) float g_thr[NTOK];
__device__ alignas(256) __half g_ats[2*PL_AT];
__device__ alignas(256) __half g_Was[2*PL_WA];
__device__ alignas(256) float g_r  [NTOK*512];
__device__ alignas(256) __half g_rns[2*PL_RN];
__device__ alignas(256) __half g_Wbs[2*PL_WB];

// ---------------- helpers ----------------
__device__ __forceinline__ void cpa16(uint32_t dst, const void* src) {
    asm volatile("cp.async.cg.shared.global [%0], [%1], 16;\n" :: "r"(dst), "l"(src));
}
__device__ __forceinline__ void cp_commit() {
    asm volatile("cp.async.commit_group;\n");
}
// k-permutation within a 32-element group: u32 j -> ((j&3)<<2)|(j>>2)
__device__ __forceinline__ int permk(int idx) {
    int kk = idx & 31;
    int j = kk >> 1;
    int jn = ((j & 3) << 2) | (j >> 2);
    return (idx & ~31) | (jn << 1) | (kk & 1);
}
// fp16 2-way split with permuted k index
__device__ __forceinline__ void split2(float v, __half* p, size_t base, int kidx, long plane) {
    __half h0 = __float2half_rn(v);
    float r1 = v - __half2float(h0);
    size_t idx = base + (size_t)permk(kidx);
    p[idx]         = h0;
    p[idx + plane] = __float2half_rn(r1);
}
__device__ __forceinline__ void mma_f16(float* c,
    uint32_t a0, uint32_t a1, uint32_t a2, uint32_t a3,
    uint32_t b0, uint32_t b1) {
    asm volatile(
        "mma.sync.aligned.m16n8k16.row.col.f32.f16.f16.f32 "
        "{%0,%1,%2,%3},{%4,%5,%6,%7},{%8,%9},{%0,%1,%2,%3};"
        : "+f"(c[0]), "+f"(c[1]), "+f"(c[2]), "+f"(c[3])
        : "r"(a0), "r"(a1), "r"(a2), "r"(a3), "r"(b0), "r"(b1));
}
__device__ __forceinline__ uint4 lds128(uint32_t addr) {
    uint4 v;
    asm volatile("ld.shared.v4.u32 {%0,%1,%2,%3}, [%4];"
                 : "=r"(v.x), "=r"(v.y), "=r"(v.z), "=r"(v.w) : "r"(addr));
    return v;
}

// ---------------- fp16 split MMA GEMM: C = alpha * A[M,K] @ B[N,K]^T ----------------
// NT=3: a0b0+a0b1+a1b0 (fp32-accurate ~2^-24). NT=2: a0b0+a0b1 (~2e-4 rel).
// A, B as 2 fp16 split planes (NT=2 reads only A plane0), k-permuted per 32-group.
// BM=BN=128, BK=32, 256 threads (8 warps 2x4), warp tile 64x32. ldc = C row stride.
// 3-stage cp.async pipeline. causal=1: skip tiles with bm+124 < 4*bn (never read).
#define HPLANE 2048          // 128 rows * 16 u32
#define HBUF   4096          // 2 planes
#define HTOT   8192          // A + B per buffer
#define HSMEM  (3 * HTOT * 4)  // 98304 bytes (3 stages)

template<int NT>
__global__ void __launch_bounds__(256, 2) mma_gemm_hx(
    int M, int N, int K, int ldc, float alpha, int causal,
    const __half* __restrict__ A0, long planeA, long batA,
    const __half* __restrict__ B0, long planeB, long batB,
    float* __restrict__ C, long batC) {
    extern __shared__ char smraw[];
    uint32_t sbase = (uint32_t)__cvta_generic_to_shared(smraw);

    const int tid  = threadIdx.x;
    const int wid  = tid >> 5;
    const int lane = tid & 31;
    const int lm   = lane >> 2;     // 0..7
    const int lk   = lane & 3;      // 0..3
    const int warp_m = (wid & 1) * 64;
    const int warp_n = (wid >> 1) * 32;
    const int bm = blockIdx.y * 128;
    const int bn = blockIdx.x * 128;
    const int z  = blockIdx.z;

    if (causal && (bm + 124 < 4 * bn)) return;   // tile fully causally masked

    const __half* Abase = A0 + (size_t)z * batA;
    const __half* Bbase = B0 + (size_t)z * batB;
    float* Cptr = C + (size_t)z * batC + (size_t)(bm + warp_m) * ldc + bn + warp_n;

    float c[4][4][4];
    #pragma unroll
    for (int mt = 0; mt < 4; mt++)
        #pragma unroll
        for (int nt = 0; nt < 4; nt++)
            #pragma unroll
            for (int i = 0; i < 4; i++) c[mt][nt][i] = 0.f;

    const int nIter = K >> 5;

    auto stage = [&](int it, int buf) {
        const int k0 = it * 32;
        const uint32_t abase = sbase + (uint32_t)(buf * HTOT) * 4u;
        const uint32_t bbase = abase + HBUF * 4u;
        #pragma unroll
        for (int i = 0; i < (NT == 2 ? 2 : 4); i++) {
            int id = tid + i * 256;
            int p = id >> 9, rem = id & 511, row = rem >> 2, cc = rem & 3;
            cpa16(abase + (uint32_t)(p * HPLANE + row * 16 + cc * 4) * 4u,
                  Abase + (size_t)p * planeA + (size_t)(bm + row) * K + k0 + cc * 8);
        }
        #pragma unroll
        for (int i = 0; i < 4; i++) {
            int id = tid + i * 256;
            int p = id >> 9, rem = id & 511, row = rem >> 2, cc = rem & 3;
            cpa16(bbase + (uint32_t)(p * HPLANE + row * 16 + cc * 4) * 4u,
                  Bbase + (size_t)p * planeB + (size_t)(bn + row) * K + k0 + cc * 8);
        }
        cp_commit();
    };

    stage(0, 0);
    if (nIter > 1) stage(1, 1);

    int buf = 0;
    for (int it = 0; it < nIter; it++) {
        if (it + 1 < nIter) {
            asm volatile("cp.async.wait_group 1;\n" ::: "memory");
        } else {
            asm volatile("cp.async.wait_group 0;\n" ::: "memory");
        }
        __syncthreads();
        if (it + 2 < nIter) stage(it + 2, (buf + 2 >= 3) ? buf - 1 : buf + 2);

        const uint32_t abufb = sbase + (uint32_t)(buf * HTOT) * 4u;
        const uint32_t bbufb = abufb + HBUF * 4u;

        uint4 b0f[4], b1f[4];
        #pragma unroll
        for (int nt = 0; nt < 4; nt++) {
            uint32_t baddr = bbufb + (uint32_t)(warp_n + nt * 8 + lm) * 64u + lk * 16u;
            b0f[nt] = lds128(baddr);
            b1f[nt] = lds128(baddr + HPLANE * 4u);
        }

        #pragma unroll
        for (int mt = 0; mt < 4; mt++) {
            const uint32_t aaddr = abufb + (uint32_t)(warp_m + mt * 16 + lm) * 64u + lk * 16u;
            uint4 alo0 = lds128(aaddr);
            uint4 ahi0 = lds128(aaddr + 8u * 64u);
            #pragma unroll
            for (int nt = 0; nt < 4; nt++)
                mma_f16(c[mt][nt], alo0.x, ahi0.x, alo0.y, ahi0.y, b0f[nt].x, b0f[nt].y);
            #pragma unroll
            for (int nt = 0; nt < 4; nt++)
                mma_f16(c[mt][nt], alo0.x, ahi0.x, alo0.y, ahi0.y, b1f[nt].x, b1f[nt].y);
            #pragma unroll
            for (int nt = 0; nt < 4; nt++)
                mma_f16(c[mt][nt], alo0.z, ahi0.z, alo0.w, ahi0.w, b0f[nt].z, b0f[nt].w);
            #pragma unroll
            for (int nt = 0; nt < 4; nt++)
                mma_f16(c[mt][nt], alo0.z, ahi0.z, alo0.w, ahi0.w, b1f[nt].z, b1f[nt].w);
            if (NT == 3) {
                uint4 alo1 = lds128(aaddr + HPLANE * 4u);
                uint4 ahi1 = lds128(aaddr + HPLANE * 4u + 8u * 64u);
                #pragma unroll
                for (int nt = 0; nt < 4; nt++)
                    mma_f16(c[mt][nt], alo1.x, ahi1.x, alo1.y, ahi1.y, b0f[nt].x, b0f[nt].y);
                #pragma unroll
                for (int nt = 0; nt < 4; nt++)
                    mma_f16(c[mt][nt], alo1.z, ahi1.z, alo1.w, ahi1.w, b0f[nt].z, b0f[nt].w);
            }
        }
        buf = (buf + 1 >= 3) ? 0 : buf + 1;
    }

    #pragma unroll
    for (int mt = 0; mt < 4; mt++) {
        #pragma unroll
        for (int nt = 0; nt < 4; nt++) {
            int r0 = mt * 16 + lm;
            int cc = nt * 8 + 2 * lk;
            float2 v;
            v.x = c[mt][nt][0] * alpha; v.y = c[mt][nt][1] * alpha;
            *(float2*)(Cptr + (size_t)r0 * ldc + cc) = v;
            v.x = c[mt][nt][2] * alpha; v.y = c[mt][nt][3] * alpha;
            *(float2*)(Cptr + (size_t)(r0 + 8) * ldc + cc) = v;
        }
    }
}

// ---------------- split kernels (write permuted k layout) ----------------
__global__ void split_plain(const float* __restrict__ src, __half* dst,
                            long plane, int n) {
    int idx = blockIdx.x * 256 + threadIdx.x;
    if (idx < n) split2(src[idx], dst, (size_t)(idx & ~31), idx & 31, plane);
}

// value-column weight concat+transpose+split: cols [0,2560) = q|ck|cv|cg
__global__ void splitT_w7_val(const float* __restrict__ Wq,  const float* __restrict__ Wck,
                              const float* __restrict__ Wcv, const float* __restrict__ Wcg,
                              __half* out) {
    __shared__ float tile[32][33];
    int k0 = blockIdx.x * 32, n0 = blockIdx.y * 32;
    int tx = threadIdx.x, ty = threadIdx.y;
    {
        int k = k0 + ty, n = n0 + tx;
        float v;
        if      (n < 1024) v = Wq [k * 1024 + n];
        else if (n < 1536) v = Wck[k * 512 + n - 1024];
        else if (n < 2048) v = Wcv[k * 512 + n - 1536];
        else               v = Wcg[k * 512 + n - 2048];
        tile[ty][tx] = v;
    }
    __syncthreads();
    int n = n0 + ty, k = k0 + tx;
    split2(tile[tx][ty], out, (size_t)n * 1024 + (k & ~31), k & 31, PL_WT);
}

// selection-column weight concat+transpose+split: cols [2560,4096) = ig|iq|ik
__global__ void splitT_w7_sel(const float* __restrict__ Wig, const float* __restrict__ Wiq,
                              const float* __restrict__ Wik, __half* out) {
    __shared__ float tile[32][33];
    int k0 = blockIdx.x * 32, n0 = blockIdx.y * 32;   // n0 over [0,1536)
    int tx = threadIdx.x, ty = threadIdx.y;
    {
        int k = k0 + ty, n = n0 + tx;
        float v;
        if      (n < 512)  v = Wig[k * 512 + n];
        else if (n < 1024) v = Wiq[k * 512 + n - 512];
        else               v = Wik[k * 512 + n - 1024];
        tile[ty][tx] = v;
    }
    __syncthreads();
    int n = 2560 + n0 + ty, k = k0 + tx;
    split2(tile[tx][ty], out, (size_t)n * 1024 + (k & ~31), k & 31, PL_WT);
}

// generic transpose+split: src [Kd][Nd] -> out planes [Nd][Kd]
__global__ void splitT_gen(const float* __restrict__ src, __half* out,
                           int Kd, int Nd, long plane) {
    __shared__ float tile[32][33];
    int k0 = blockIdx.x * 32, n0 = blockIdx.y * 32;
    int tx = threadIdx.x, ty = threadIdx.y;
    tile[ty][tx] = src[(size_t)(k0 + ty) * Nd + n0 + tx];
    __syncthreads();
    int n = n0 + ty, k = k0 + tx;
    split2(tile[tx][ty], out, (size_t)n * Kd + (k & ~31), k & 31, plane);
}

// ---------------- rope helper ----------------
__device__ __forceinline__ void rope_cs(int i, float pos, float& c, float& s) {
    float f = powf(160000.0f, (float)i * (1.0f / 32.0f));
    float ang = pos / f;
    sincosf(ang, &s, &c);
}

// ---------------- gated compress (coarse KV) + rope on ck ---------------- grid Bb*Gg*HKV, block 128
__global__ void compress_c(const float* __restrict__ ape) {
    int blk = blockIdx.x;
    int h = blk & 3;
    int bg = blk >> 2;
    int g = bg & (Gg - 1);
    int d = threadIdx.x;
    size_t base = (size_t)bg * 4 * NCOL + h * 128 + d;
    float gv[4], m = -1e30f;
    #pragma unroll
    for (int r = 0; r < 4; r++) {
        gv[r] = g_Pall[base + (size_t)r * NCOL + OFF_CG] + ape[(r * HKV + h) * 128 + d];
        m = fmaxf(m, gv[r]);
    }
    float ssum = 0.f;
    #pragma unroll
    for (int r = 0; r < 4; r++) { gv[r] = expf(gv[r] - m); ssum += gv[r]; }
    float inv = 1.f / ssum;
    float ka = 0.f, va = 0.f;
    #pragma unroll
    for (int r = 0; r < 4; r++) {
        float w = gv[r] * inv;
        ka += w * g_Pall[base + (size_t)r * NCOL + OFF_CK];
        va += w * g_Pall[base + (size_t)r * NCOL + OFF_CV];
    }
    __shared__ float sk[128];
    sk[d] = ka;
    __syncthreads();
    float pos = (float)(4 * g + 3);
    float outk = ka;
    if (d >= 64 && d < 96) {
        int i = d - 64; float c, s; rope_cs(i, pos, c, s);
        outk = sk[d] * c - sk[d + 32] * s;
    } else if (d >= 96) {
        int i = d - 96; float c, s; rope_cs(i, pos, c, s);
        outk = sk[d - 32] * s + sk[d] * c;
    }
    size_t ob = ((size_t)bg * 4 + h) * 128 + d;
    g_ck[ob] = outk;
    g_cv[ob] = va;
}

// ---------------- gated compress (index KV) + rmsnorm -> ik splits ---------------- grid Bb*Gg*HIi, block 64
__global__ void compress_i(const float* __restrict__ ape) {
    int blk = blockIdx.x;
    int h = blk & 7;
    int bg = blk >> 3;
    int d = threadIdx.x;
    size_t base = (size_t)bg * 4 * NCOL + h * 64 + d;
    float gv[4], m = -1e30f;
    #pragma unroll
    for (int r = 0; r < 4; r++) {
        gv[r] = g_Pall[base + (size_t)r * NCOL + OFF_IG] + ape[(r * HIi + h) * 64 + d];
        m = fmaxf(m, gv[r]);
    }
    float ssum = 0.f;
    #pragma unroll
    for (int r = 0; r < 4; r++) { gv[r] = expf(gv[r] - m); ssum += gv[r]; }
    float inv = 1.f / ssum;
    float ka = 0.f;
    #pragma unroll
    for (int r = 0; r < 4; r++)
        ka += gv[r] * inv * g_Pall[base + (size_t)r * NCOL + OFF_IK];
    __shared__ float red[64];
    red[d] = ka * ka;
    __syncthreads();
    #pragma unroll
    for (int s2 = 32; s2 > 0; s2 >>= 1) {
        if (d < s2) red[d] += red[d + s2];
        __syncthreads();
    }
    float sc = rsqrtf(red[0] / 64.f + 1e-6f);
    split2(ka * sc, g_iks, (size_t)bg * 512 + h * 64 + (d & ~31), d & 31, PL_IK);
}

// ---------------- per-head rmsnorm of iq -> iq splits ---------------- grid NTOK*HIi, block 64
__global__ void iq_rms() {
    int blk = blockIdx.x;
    int h = blk & 7;
    int row = blk >> 3;
    int d = threadIdx.x;
    float v = g_Pall[(size_t)row * NCOL + OFF_IQ + h * 64 + d];
    __shared__ float red[64];
    red[d] = v * v;
    __syncthreads();
    #pragma unroll
    for (int s2 = 32; s2 > 0; s2 >>= 1) {
        if (d < s2) red[d] += red[d + s2];
        __syncthreads();
    }
    float sc = rsqrtf(red[0] / 64.f + 1e-6f);
    split2(v * sc, g_iqs, (size_t)row * 512 + h * 64 + (d & ~31), d & 31, PL_IQ);
}

// ---------------- in-place partial rope of q ---------------- grid NTOK*Hh, block 32
__global__ void q_rope() {
    int blk = blockIdx.x;
    int h = blk & 7;
    int row = blk >> 3;
    int t = row & (Tt - 1);
    int i = threadIdx.x;
    size_t base = (size_t)row * NCOL + OFF_Q + h * 128;
    float x1 = g_Pall[base + 64 + i];
    float x2 = g_Pall[base + 96 + i];
    float c, s; rope_cs(i, (float)t, c, s);
    g_Pall[base + 64 + i] = x1 * c - x2 * s;
    g_Pall[base + 96 + i] = x1 * s + x2 * c;
}

// ---------------- top-k(64) threshold via hybrid bitonic sort ---------------- grid NTOK, block 512
__global__ void topk_thresh() {
    __shared__ float s[512];
    int row = blockIdx.x;
    int t = row & (Tt - 1);
    int tid = threadIdx.x;
    float v = g_isc[(size_t)row * Gg + tid];
    if (4 * tid + 3 > t) v = NEGv;

    #pragma unroll
    for (int k = 2; k <= 32; k <<= 1) {
        #pragma unroll
        for (int j = k >> 1; j > 0; j >>= 1) {
            float p = __shfl_xor_sync(0xffffffffu, v, j);
            bool down  = ((tid & k) == 0);
            bool lower = ((tid & j) == 0);
            v = (lower == down) ? fmaxf(v, p) : fminf(v, p);
        }
    }
    s[tid] = v;
    __syncthreads();

    for (int k = 64; k <= 512; k <<= 1) {
        for (int j = k >> 1; j >= 32; j >>= 1) {
            int ixj = tid ^ j;
            if (ixj > tid) {
                float a = s[tid], b = s[ixj];
                bool down = ((tid & k) == 0);
                bool sw = down ? (a < b) : (a > b);
                if (sw) { s[tid] = b; s[ixj] = a; }
            }
            __syncthreads();
        }
        v = s[tid];
        #pragma unroll
        for (int j = 16; j > 0; j >>= 1) {
            float p = __shfl_xor_sync(0xffffffffu, v, j);
            bool down  = ((tid & k) == 0);
            bool lower = ((tid & j) == 0);
            v = (lower == down) ? fmaxf(v, p) : fminf(v, p);
        }
        if (k < 512) { s[tid] = v; __syncthreads(); }
    }
    if (tid == 63) g_thr[row] = v;
}

// ---------------- sparse attention, all 8 heads per block -> at splits ----------------
// grid NTOK, block 256. Warp w computes scores+softmax for head w (hkv=w>>1).
// V phase: thread (j0 = tid>>7, d = tid&127) accumulates heads {2j0,2j0+1,2j0+4,2j0+5}.
__global__ void __launch_bounds__(256) attn_kernel() {
    int row = blockIdx.x;
    int t = row & (Tt - 1);
    int b = row >> 11;
    int tid = threadIdx.x;
    int warp = tid >> 5, lane = tid & 31;
    __shared__ int sg[96];
    __shared__ float sw[8][96];
    __shared__ alignas(16) float qsh[1024];
    __shared__ int cnt;
    if (tid == 0) cnt = 0;
    __syncthreads();

    int nc = (t >= 3) ? (((t - 3) >> 2) + 1) : 0;
    float th = g_thr[row];
    const float* iscr = g_isc + (size_t)row * Gg;
    for (int g = tid; g < nc; g += 256) {
        if (iscr[g] >= th) {
            int p = atomicAdd(&cnt, 1);
            if (p < 96) sg[p] = g;
        }
    }
    #pragma unroll
    for (int i = 0; i < 4; i++)
        qsh[tid + i * 256] = g_Pall[(size_t)row * NCOL + OFF_Q + tid + i * 256];
    __syncthreads();
    int n = min(cnt, 96);

    // scores: warp w = head w
    {
        int hkv = warp >> 1;
        float4 qv = *(const float4*)(qsh + warp * 128 + lane * 4);
        #pragma unroll 2
        for (int i = 0; i < n; i++) {
            const float* kp = g_ck + ((size_t)(b * Gg + sg[i]) * 4 + hkv) * 128;
            float4 kv = *(const float4*)(kp + lane * 4);
            float p = qv.x * kv.x + qv.y * kv.y + qv.z * kv.z + qv.w * kv.w;
            #pragma unroll
            for (int o = 16; o > 0; o >>= 1) p += __shfl_xor_sync(0xffffffffu, p, o);
            if (lane == 0) sw[warp][i] = p * 0.0883883476483184f;
        }
    }
    __syncthreads();

    // per-head warp softmax over n entries (n <= 96)
    {
        float v0 = (lane      < n) ? sw[warp][lane]      : -1e30f;
        float v1 = (lane + 32 < n) ? sw[warp][lane + 32] : -1e30f;
        float v2 = (lane + 64 < n) ? sw[warp][lane + 64] : -1e30f;
        float m = fmaxf(v0, fmaxf(v1, v2));
        #pragma unroll
        for (int o = 16; o > 0; o >>= 1) m = fmaxf(m, __shfl_xor_sync(0xffffffffu, m, o));
        float e0 = (lane      < n) ? expf(v0 - m) : 0.f;
        float e1 = (lane + 32 < n) ? expf(v1 - m) : 0.f;
        float e2 = (lane + 64 < n) ? expf(v2 - m) : 0.f;
        float ssum = e0 + e1 + e2;
        #pragma unroll
        for (int o = 16; o > 0; o >>= 1) ssum += __shfl_xor_sync(0xffffffffu, ssum, o);
        float inv = 1.f / ssum;
        if (lane      < n) sw[warp][lane]      = e0 * inv;
        if (lane + 32 < n) sw[warp][lane + 32] = e1 * inv;
        if (lane + 64 < n) sw[warp][lane + 64] = e2 * inv;
    }
    __syncthreads();

    // V accumulation: 4 outputs per thread, V row shared by head pairs
    {
        int d = tid & 127;
        int j0 = tid >> 7;               // hkv j0 and j0+2
        float a0 = 0.f, a1 = 0.f, a2 = 0.f, a3 = 0.f;
        #pragma unroll 2
        for (int i = 0; i < n; i++) {
            size_t vb = (size_t)(b * Gg + sg[i]) * 4;
            float v0 = g_cv[(vb + j0) * 128 + d];
            float v1 = g_cv[(vb + j0 + 2) * 128 + d];
            a0 += sw[2 * j0][i]     * v0;
            a1 += sw[2 * j0 + 1][i] * v0;
            a2 += sw[2 * j0 + 4][i] * v1;
            a3 += sw[2 * j0 + 5][i] * v1;
        }
        size_t ob = (size_t)row * 1024 + (d & ~31);
        int kb = d & 31;
        split2(a0, g_ats, ob + (2 * j0) * 128,     kb, PL_AT);
        split2(a1, g_ats, ob + (2 * j0 + 1) * 128, kb, PL_AT);
        split2(a2, g_ats, ob + (2 * j0 + 4) * 128, kb, PL_AT);
        split2(a3, g_ats, ob + (2 * j0 + 5) * 128, kb, PL_AT);
    }
}

// ---------------- rmsnorm over RANK=512 -> rn splits ---------------- grid NTOK, block 256
__global__ void rmsnorm512() {
    int row = blockIdx.x;
    int tid = threadIdx.x;
    size_t base = (size_t)row * 512;
    float a = g_r[base + tid], b = g_r[base + 256 + tid];
    __shared__ float red[256];
    red[tid] = a * a + b * b;
    __syncthreads();
    #pragma unroll
    for (int s2 = 128; s2 > 0; s2 >>= 1) {
        if (tid < s2) red[tid] += red[tid + s2];
        __syncthreads();
    }
    float sc = rsqrtf(red[0] / 512.f + 1e-6f);
    split2(a * sc, g_rns, base + (tid & ~31), tid & 31, PL_RN);
    split2(b * sc, g_rns, base + 256 + (tid & ~31), tid & 31, PL_RN);
}

// ---------------- launch ----------------
extern "C" void kernel_launch(void* const* d_in, const int* in_sizes, int n_in,
                              void* d_out, int out_size) {
    const float* x     = (const float*)d_in[0];
    const float* Wq    = (const float*)d_in[1];
    const float* Wck   = (const float*)d_in[2];
    const float* Wcv   = (const float*)d_in[3];
    const float* Wcg   = (const float*)d_in[4];
    const float* ape_c = (const float*)d_in[5];
    const float* Wiq   = (const float*)d_in[6];
    const float* Wik   = (const float*)d_in[7];
    const float* Wig   = (const float*)d_in[8];
    const float* ape_i = (const float*)d_in[9];
    const float* Wa    = (const float*)d_in[10];
    const float* Wb    = (const float*)d_in[11];
    float* out = (float*)d_out;

    __half *xs, *WTs, *iks, *iqs, *ats, *Was, *rns, *Wbs;
    float *Pall, *isc, *r;
    cudaGetSymbolAddress((void**)&xs,   g_xs);
    cudaGetSymbolAddress((void**)&WTs,  g_WTs);
    cudaGetSymbolAddress((void**)&Pall, g_Pall);
    cudaGetSymbolAddress((void**)&iks,  g_iks);
    cudaGetSymbolAddress((void**)&iqs,  g_iqs);
    cudaGetSymbolAddress((void**)&isc,  g_isc);
    cudaGetSymbolAddress((void**)&ats,  g_ats);
    cudaGetSymbolAddress((void**)&Was,  g_Was);
    cudaGetSymbolAddress((void**)&r,    g_r);
    cudaGetSymbolAddress((void**)&rns,  g_rns);
    cudaGetSymbolAddress((void**)&Wbs,  g_Wbs);

    static cudaStream_t s2 = 0;
    static cudaEvent_t evA, evX, evWv, ev3, evKV, evCC;
    static int attr_set = 0;
    if (!attr_set) {
        cudaFuncSetAttribute(mma_gemm_hx<2>, cudaFuncAttributeMaxDynamicSharedMemorySize, HSMEM);
        cudaFuncSetAttribute(mma_gemm_hx<3>, cudaFuncAttributeMaxDynamicSharedMemorySize, HSMEM);
        cudaStreamCreateWithFlags(&s2, cudaStreamNonBlocking);
        cudaEventCreateWithFlags(&evA,  cudaEventDisableTiming);
        cudaEventCreateWithFlags(&evX,  cudaEventDisableTiming);
        cudaEventCreateWithFlags(&evWv, cudaEventDisableTiming);
        cudaEventCreateWithFlags(&ev3,  cudaEventDisableTiming);
        cudaEventCreateWithFlags(&evKV, cudaEventDisableTiming);
        cudaEventCreateWithFlags(&evCC, cudaEventDisableTiming);
        attr_set = 1;
    }

    // fork: s2 does x split, value-col weight split, Wa/Wb splits
    cudaEventRecord(evA, 0);
    cudaStreamWaitEvent(s2, evA, 0);
    split_plain<<<(NTOK * 1024) / 256, 256, 0, s2>>>(x, xs, PL_X, NTOK * 1024);
    cudaEventRecord(evX, s2);
    splitT_w7_val<<<dim3(1024 / 32, 2560 / 32), dim3(32, 32), 0, s2>>>(Wq, Wck, Wcv, Wcg, WTs);
    cudaEventRecord(evWv, s2);
    split_plain<<<(512 * 1024) / 256, 256, 0, s2>>>(Wa, Was, PL_WA, 512 * 1024);
    splitT_gen<<<dim3(512 / 32, 1024 / 32), dim3(32, 32), 0, s2>>>(Wb, Wbs, 512, 1024, PL_WB);

    // main: selection weight split + 3-term projection (selection columns)
    splitT_w7_sel<<<dim3(1024 / 32, 1536 / 32), dim3(32, 32)>>>(Wig, Wiq, Wik, WTs);
    cudaStreamWaitEvent(0, evX, 0);
    mma_gemm_hx<3><<<dim3((NCOL - SPLIT_COL) / 128, NTOK / 128, 1), 256, HSMEM>>>(
        NTOK, NCOL - SPLIT_COL, 1024, NCOL, 1.f, 0, xs, PL_X, 0,
        WTs + (size_t)SPLIT_COL * 1024, PL_WT, 0, Pall + SPLIT_COL, 0);
    cudaEventRecord(ev3, 0);

    // s2: selection chain runs concurrently with the 2-term projections below
    cudaStreamWaitEvent(s2, ev3, 0);
    compress_i<<<Bb * Gg * HIi, 64, 0, s2>>>(ape_i);
    iq_rms<<<NTOK * HIi, 64, 0, s2>>>();
    mma_gemm_hx<3><<<dim3(512 / 128, 2048 / 128, Bb), 256, HSMEM, s2>>>(
        2048, 512, 512, 512, 1.f / 64.f, 1,
        iqs, PL_IQ, (long)2048 * 512,
        iks, PL_IK, (long)512 * 512,
        isc, (long)2048 * 512);
    topk_thresh<<<NTOK, 512, 0, s2>>>();

    // main: 2-term projection, kv columns first
    cudaStreamWaitEvent(0, evWv, 0);
    mma_gemm_hx<2><<<dim3(1536 / 128, NTOK / 128, 1), 256, HSMEM>>>(
        NTOK, 1536, 1024, NCOL, 1.f, 0, xs, PL_X, 0,
        WTs + (size_t)1024 * 1024, PL_WT, 0, Pall + 1024, 0);
    cudaEventRecord(evKV, 0);

    // s2: compress_c overlaps with the q projection on main
    cudaStreamWaitEvent(s2, evKV, 0);
    compress_c<<<Bb * Gg * HKV, 128, 0, s2>>>(ape_c);
    cudaEventRecord(evCC, s2);

    // main: q projection + rope
    mma_gemm_hx<2><<<dim3(1024 / 128, NTOK / 128, 1), 256, HSMEM>>>(
        NTOK, 1024, 1024, NCOL, 1.f, 0, xs, PL_X, 0, WTs, PL_WT, 0, Pall, 0);
    q_rope<<<NTOK * Hh, 32>>>();

    // join: attn needs selection + compress_c (s2) + q (main)
    cudaStreamWaitEvent(0, evCC, 0);
    attn_kernel<<<NTOK, 256>>>();

    // r = attn @ Wa^T (2-term)
    mma_gemm_hx<2><<<dim3(512 / 128, NTOK / 128, 1), 256, HSMEM>>>(
        NTOK, 512, 1024, 512, 1.f, 0, ats, PL_AT, 0, Was, PL_WA, 0, r, 0);

    rmsnorm512<<<NTOK, 256>>>();

    // out = rn @ Wb (2-term)
    mma_gemm_hx<2><<<dim3(1024 / 128, NTOK / 128, 1), 256, HSMEM>>>(
        NTOK, 1024, 512, 1024, 1.f, 0, rns, PL_RN, 0, Wbs, PL_WB, 0, out, 0);
}